// round 3
// baseline (speedup 1.0000x reference)
#include <cuda_runtime.h>
#include <cuda_bf16.h>

// Problem constants
#define BB   16
#define DD   128
#define TT   4096
#define NN   (BB * TT)        // 65536 rows
#define NC   1024             // codebook size
#define QELEMS (BB * DD * TT) // 8388608

// ---------------- device scratch (no allocation allowed) ----------------
__device__ int   g_indices[NN];
__device__ float g_partial[NN / 64];   // per-block d2 sums (1024 blocks)
__device__ float g_used[NC];
__device__ float g_enorm[NC];

// ---------------- packed f32x2 helpers (FFMA2: 2 MACs/instr) ----------------
__device__ __forceinline__ unsigned long long fma2(unsigned long long a,
                                                   unsigned long long b,
                                                   unsigned long long c) {
    unsigned long long d;
    asm("fma.rn.f32x2 %0, %1, %2, %3;" : "=l"(d) : "l"(a), "l"(b), "l"(c));
    return d;
}
__device__ __forceinline__ float2 unpack2(unsigned long long v) {
    float2 r;
    asm("mov.b64 {%0, %1}, %2;" : "=f"(r.x), "=f"(r.y) : "l"(v));
    return r;
}

// ---------------- kernel 0: code norms + zero used flags ----------------
__global__ void vq_init(const float* __restrict__ embed) {
    int c = blockIdx.x * 256 + threadIdx.x;
    if (c < NC) {
        const float4* e4 = reinterpret_cast<const float4*>(embed + (size_t)c * DD);
        float s = 0.f;
        #pragma unroll
        for (int i = 0; i < DD / 4; ++i) {
            float4 v = e4[i];
            s += v.x * v.x + v.y * v.y + v.z * v.z + v.w * v.w;
        }
        g_enorm[c] = s;
        g_used[c] = 0.f;
    }
}

// ---------------- kernel 1: fused distance-GEMM + argmin ----------------
// Block: 64 rows x 1024 codes (16 tiles of 64). 256 threads (16x16); each
// thread owns a 4x4 (row x code) microtile, k-pair-packed f32x2 accumulators.
//
// Numerics: the comparison value is built EXACTLY like the reference —
//   d2 = (rowsq - 2*dot) + enorm, each step f32-rounded, no FMA fusion —
// so d2 lives on the same ~7.6e-6 grid (ulp at ~128) as the reference and
// quantized ties resolve identically (lowest index wins on both sides).
//
// e tile: es[c][k], stride 128 floats, 16B-chunk XOR swizzle
//   chunk' = chunk ^ ((c>>2)&7); loop-invariant per thread ((cb+j)>>2 == tx)
//   -> conflict-free LDS.128 reads and STS.128 transpose writes.
#define SPAD 132

__global__ void __launch_bounds__(256) vq_argmin(const float* __restrict__ x,
                                                 const float* __restrict__ embed) {
    extern __shared__ float sm[];
    float* xs     = sm;                  // [64][SPAD]
    float* es     = xs + 64 * SPAD;      // [64][128] swizzled
    float* rowsq  = es + 64 * 128;       // [64]
    float* rowmin = rowsq + 64;          // [64]
    int*   rowidx = (int*)(rowmin + 64); // [64]

    const int tid = threadIdx.x;
    const int tx = tid & 15, ty = tid >> 4;
    const int blk = blockIdx.x;
    const int n0 = blk * 64;
    const int bb = n0 >> 12;             // / 4096
    const int t0 = n0 & 4095;
    const float* xb = x + (size_t)bb * DD * TT;

    // Load x tile transposed: xs[t][d]; float4 along t (coalesced gmem)
    #pragma unroll
    for (int it = 0; it < 8; ++it) {
        int f = tid + it * 256;          // 0..2047
        int d = f >> 4;                  // 0..127
        int v = f & 15;                  // float4 index along t
        float4 val = *reinterpret_cast<const float4*>(xb + (size_t)d * TT + t0 + v * 4);
        xs[(v * 4 + 0) * SPAD + d] = val.x;
        xs[(v * 4 + 1) * SPAD + d] = val.y;
        xs[(v * 4 + 2) * SPAD + d] = val.z;
        xs[(v * 4 + 3) * SPAD + d] = val.w;
    }
    __syncthreads();

    if (tid < 64) {
        float s = 0.f;
        #pragma unroll 8
        for (int k = 0; k < DD; ++k) { float v = xs[tid * SPAD + k]; s += v * v; }
        rowsq[tid] = s;
    }

    float best[4];
    int   bidx[4];
    #pragma unroll
    for (int i = 0; i < 4; ++i) { best[i] = 3.4e38f; bidx[i] = 0; }

    const int r0 = ty * 4;
    const int cb = tx * 4;
    const int sx = tx & 7;               // loop-invariant swizzle term

    float rq[4];                         // per-row ||x||^2, loaded after ct=0 sync
    bool rq_loaded = false;

    for (int ct = 0; ct < 16; ++ct) {
        const int c0 = ct * 64;
        __syncthreads();  // guard es overwrite vs previous tile readers; makes rowsq visible
        if (!rq_loaded) {
            #pragma unroll
            for (int i = 0; i < 4; ++i) rq[i] = rowsq[r0 + i];  // broadcast LDS
            rq_loaded = true;
        }
        // Load + swizzle-transpose e tile: es[c][k], STS.128 conflict-free
        #pragma unroll
        for (int it = 0; it < 8; ++it) {
            int f  = tid + it * 256;     // 0..2047
            int cc = f >> 5;             // 0..63 (constant per warp)
            int v  = f & 31;             // 16B-chunk index along k
            float4 val = *reinterpret_cast<const float4*>(embed + (size_t)(c0 + cc) * DD + v * 4);
            int vs = v ^ ((cc >> 2) & 7);
            *reinterpret_cast<float4*>(es + cc * 128 + vs * 4) = val;
        }
        __syncthreads();

        unsigned long long acc[4][4];
        #pragma unroll
        for (int i = 0; i < 4; ++i)
            #pragma unroll
            for (int j = 0; j < 4; ++j) acc[i][j] = 0ull;  // (0.0f, 0.0f)

        #pragma unroll 4
        for (int kc = 0; kc < 32; ++kc) {       // 16B chunk = 4 k values
            const int k  = kc * 4;
            const int ko = (kc ^ sx) * 4;       // swizzled k offset for es
            ulonglong2 xu[4], eu[4];
            #pragma unroll
            for (int i = 0; i < 4; ++i)
                xu[i] = *reinterpret_cast<const ulonglong2*>(xs + (r0 + i) * SPAD + k);
            #pragma unroll
            for (int j = 0; j < 4; ++j)
                eu[j] = *reinterpret_cast<const ulonglong2*>(es + (cb + j) * 128 + ko);
            #pragma unroll
            for (int i = 0; i < 4; ++i) {
                #pragma unroll
                for (int j = 0; j < 4; ++j) {
                    acc[i][j] = fma2(xu[i].x, eu[j].x, acc[i][j]);
                    acc[i][j] = fma2(xu[i].y, eu[j].y, acc[i][j]);
                }
            }
        }

        #pragma unroll
        for (int j = 0; j < 4; ++j) {
            int c = c0 + cb + j;
            float en = __ldg(&g_enorm[c]);
            #pragma unroll
            for (int i = 0; i < 4; ++i) {
                float2 p = unpack2(acc[i][j]);
                float dot = __fadd_rn(p.x, p.y);
                // match reference rounding chain: (||x||^2 - 2*dot) + ||e||^2
                float m  = __fmul_rn(2.0f, dot);
                float t1 = __fsub_rn(rq[i], m);
                float s  = __fadd_rn(t1, en);
                if (s < best[i]) { best[i] = s; bidx[i] = c; }  // ascending c -> first-wins
            }
        }
    }

    // cross-thread argmin reduce over the 16 tx lanes (within warp half)
    #pragma unroll
    for (int off = 8; off >= 1; off >>= 1) {
        #pragma unroll
        for (int i = 0; i < 4; ++i) {
            float ov = __shfl_xor_sync(0xffffffffu, best[i], off);
            int   oi = __shfl_xor_sync(0xffffffffu, bidx[i], off);
            if (ov < best[i] || (ov == best[i] && oi < bidx[i])) { best[i] = ov; bidx[i] = oi; }
        }
    }
    if (tx == 0) {
        #pragma unroll
        for (int i = 0; i < 4; ++i) { rowmin[r0 + i] = best[i]; rowidx[r0 + i] = bidx[i]; }
    }
    __syncthreads();

    if (tid < 64) {
        int c = rowidx[tid];
        g_indices[n0 + tid] = c;
        g_used[c] = 1.0f;                       // idempotent, race-free
    }
    if (tid == 0) {
        float s = 0.f;
        #pragma unroll 8
        for (int r = 0; r < 64; ++r) s += rowmin[r];  // fixed order -> deterministic
        g_partial[blk] = s;                           // sum of min d2 (incl ||x||^2)
    }
}

// ---------------- kernel 2: gather + transposed write (+ indices as f32) ----------------
#define WPAD 133  // (t*133 + d) % 32 = (5t + d) % 32 -> conflict-free transposed reads

__global__ void __launch_bounds__(256) vq_write(const float* __restrict__ embed,
                                                float* __restrict__ out,
                                                int write_idx) {
    extern __shared__ float sm[];
    int*   sidx = (int*)sm;        // [128]
    float* srow = sm + 128;        // [128][WPAD]

    const int tid = threadIdx.x;
    const int tt = blockIdx.x;     // 0..31  (t tile of 128)
    const int bb = blockIdx.y;     // 0..15
    const int t0 = tt * 128;
    const int nbase = bb * TT + t0;

    if (tid < 128) {
        int c = g_indices[nbase + tid];
        sidx[tid] = c;
        if (write_idx) out[(size_t)QELEMS + nbase + tid] = (float)c;
    }
    __syncthreads();

    // gather 128 embed rows into smem (embed is L2-resident)
    #pragma unroll 4
    for (int it = 0; it < 16; ++it) {
        int f = tid + it * 256;    // 0..4095
        int tl = f >> 5;           // 0..127
        int v  = f & 31;
        float4 val = *reinterpret_cast<const float4*>(embed + (size_t)sidx[tl] * DD + v * 4);
        float* dst = srow + tl * WPAD + v * 4;
        dst[0] = val.x; dst[1] = val.y; dst[2] = val.z; dst[3] = val.w;
    }
    __syncthreads();

    // write out[b][d][t] = srow[t][d]; coalesced along t
    float* ob = out + (size_t)bb * DD * TT + t0;
    #pragma unroll 8
    for (int it = 0; it < 64; ++it) {
        int f = tid + it * 256;    // 0..16383
        int d = f >> 7;
        int t = f & 127;
        ob[(size_t)d * TT + t] = srow[t * WPAD + d];
    }
}

// ---------------- kernel 3: deterministic finalize ----------------
__global__ void vq_finalize(float* __restrict__ out, int out_size) {
    __shared__ float s1[256], s2[256];
    int tid = threadIdx.x;
    float a = 0.f, b = 0.f;
    for (int i = tid; i < NN / 64; i += 256) a += g_partial[i];
    for (int i = tid; i < NC; i += 256)      b += g_used[i];
    s1[tid] = a; s2[tid] = b;
    __syncthreads();
    for (int off = 128; off > 0; off >>= 1) {
        if (tid < off) { s1[tid] += s1[tid + off]; s2[tid] += s2[tid + off]; }
        __syncthreads();
    }
    if (tid == 0) {
        long long base = (long long)QELEMS + NN;   // 8454144
        if ((long long)out_size >= base + 2) {
            out[base]     = 2.0f * s1[0] / ((float)NN * (float)DD);  // loss
            out[base + 1] = s2[0] / (float)NC;                       // utilization
        }
    }
}

// ---------------- launch ----------------
extern "C" void kernel_launch(void* const* d_in, const int* in_sizes, int n_in,
                              void* d_out, int out_size) {
    const float* x     = (const float*)d_in[0];
    const float* embed = (const float*)d_in[1];
    float* out = (float*)d_out;

    const int smem1 = (64 * SPAD + 64 * 128 + 64 * 4) * (int)sizeof(float);  // 67584 B
    const int smem2 = (128 + 128 * WPAD) * (int)sizeof(float);               // 68608 B
    cudaFuncSetAttribute(vq_argmin, cudaFuncAttributeMaxDynamicSharedMemorySize, smem1);
    cudaFuncSetAttribute(vq_write,  cudaFuncAttributeMaxDynamicSharedMemorySize, smem2);

    int write_idx = (out_size >= QELEMS + NN) ? 1 : 0;

    vq_init<<<(NC + 255) / 256, 256>>>(embed);
    vq_argmin<<<NN / 64, 256, smem1>>>(x, embed);
    dim3 g2(TT / 128, BB);
    vq_write<<<g2, 256, smem2>>>(embed, out, write_idx);
    vq_finalize<<<1, 256>>>(out, out_size);
}